// round 1
// baseline (speedup 1.0000x reference)
#include <cuda_runtime.h>
#include <math.h>

// ---------------- problem constants ----------------
#define NN   200000
#define NI   64
#define NFD  128
#define NE   256
#define BB   16
#define KK   27
#define KDD  8
#define NDD  (NN / 8)        // 25000

#define TILE_M 64
#define CHUNK  32
#define STATS_BLOCKS 512

// ---------------- scratch (device globals; no allocation allowed) ----------------
__device__ float g_a [(size_t)NN * NFD];   // activations (a1 uses [N,64], a2 uses [N,128])
__device__ float g_h [(size_t)NN * NFD];   // h after conv1 + film
__device__ float g_h2[(size_t)NN * NFD];   // h after conv2 + idconv
__device__ float g_part[STATS_BLOCKS * 2 * NFD];
__device__ float g_mv[2 * NFD];            // per-channel fused scale / shift
__device__ float g_tp[BB * 2 * NFD];       // time projection [16, 256]

__device__ __forceinline__ float silu_f(float x) {
    return x / (1.0f + expf(-x));
}

// ---------------- BN statistics: pass 1 (deterministic partial sums) ----------------
template<int C>
__global__ void bn_stats_kernel(const float* __restrict__ X, int n, float* __restrict__ part) {
    constexpr int G = 256 / C;
    __shared__ float sh[512];
    int t = threadIdx.x;
    int c = t % C, g = t / C;
    float s = 0.f, s2 = 0.f;
    for (int r = blockIdx.x * G + g; r < n; r += gridDim.x * G) {
        float v = X[(size_t)r * C + c];
        s += v; s2 += v * v;
    }
    sh[t] = s; sh[256 + t] = s2;
    __syncthreads();
    if (t < C) {
        float a = 0.f, b = 0.f;
        #pragma unroll
        for (int gg = 0; gg < G; ++gg) { a += sh[gg * C + t]; b += sh[256 + gg * C + t]; }
        part[blockIdx.x * (2 * C) + t]     = a;
        part[blockIdx.x * (2 * C) + C + t] = b;
    }
}

// ---------------- BN statistics: pass 2 (fold gamma/beta into scale+shift) ----------------
template<int C>
__global__ void bn_finalize_kernel(const float* __restrict__ part, int nblocks, float invn,
                                   const float* __restrict__ g, const float* __restrict__ be,
                                   float* __restrict__ mv) {
    int c = threadIdx.x;
    if (c >= C) return;
    float s = 0.f, s2 = 0.f;
    for (int b = 0; b < nblocks; ++b) {
        s  += part[b * 2 * C + c];
        s2 += part[b * 2 * C + C + c];
    }
    float mean = s * invn;
    float var  = s2 * invn - mean * mean;
    float istd = rsqrtf(var + 1e-5f);
    float A = istd * g[c];
    mv[c]     = A;
    mv[C + c] = be[c] - mean * A;
}

// ---------------- apply BN (fused) + SiLU, vectorized ----------------
template<int C>
__global__ void bn_apply_silu_kernel(const float4* __restrict__ X, const float* __restrict__ mv,
                                     float4* __restrict__ Y, int n4) {
    int i = blockIdx.x * 256 + threadIdx.x;
    if (i >= n4) return;
    int f = (i & (C / 4 - 1)) * 4;
    float4 v = X[i];
    float4 o;
    o.x = silu_f(fmaf(v.x, mv[f + 0], mv[C + f + 0]));
    o.y = silu_f(fmaf(v.y, mv[f + 1], mv[C + f + 1]));
    o.z = silu_f(fmaf(v.z, mv[f + 2], mv[C + f + 2]));
    o.w = silu_f(fmaf(v.w, mv[f + 3], mv[C + f + 3]));
    Y[i] = o;
}

// ---------------- time projection: tp = silu(t) @ Wt + bt   ([16,256]x[256,256]) ----------------
__global__ void tproj_kernel(const float* __restrict__ T, const float* __restrict__ Wt,
                             const float* __restrict__ bt, float* __restrict__ tp) {
    __shared__ float ts[BB * NE];
    int t = threadIdx.x;
    for (int l = t; l < BB * NE; l += 256) ts[l] = silu_f(T[l]);
    __syncthreads();
    float acc[BB];
    #pragma unroll
    for (int b = 0; b < BB; ++b) acc[b] = 0.f;
    for (int e = 0; e < NE; ++e) {
        float w = Wt[e * 256 + t];
        #pragma unroll
        for (int b = 0; b < BB; ++b) acc[b] = fmaf(ts[b * NE + e], w, acc[b]);
    }
    float bias = bt[t];
    #pragma unroll
    for (int b = 0; b < BB; ++b) tp[b * 256 + t] = acc[b] + bias;
}

// ---------------- FiLM: h = (1+scale[b_idx])*h + shift[b_idx] ----------------
__global__ void film_kernel(float4* __restrict__ H, const int* __restrict__ b_idx,
                            const float* __restrict__ tp, int total4) {
    int i = blockIdx.x * 256 + threadIdx.x;
    if (i >= total4) return;
    int n = i >> 5;             // 32 float4 per row (NF=128)
    int f = (i & 31) * 4;
    int b = b_idx[n];
    const float* sp  = tp + b * 256 + f;
    const float* shp = sp + NFD;
    float4 h = H[i];
    h.x = fmaf(sp[0], h.x, h.x) + shp[0];
    h.y = fmaf(sp[1], h.y, h.y) + shp[1];
    h.z = fmaf(sp[2], h.z, h.z) + shp[2];
    h.w = fmaf(sp[3], h.w, h.w) + shp[3];
    H[i] = h;
}

// ---------------- generic gather-GEMM (sparse conv) ----------------
// out[m, 0:128] (+)= sum_k gather(X)[m, 0:CIN] @ W[k][CIN, 128]  (+ bias)
// HAS_NBR=false -> identity gather (plain GEMM). Uses packed fma.rn.f32x2.
template<int CIN, bool ACCUM, bool HAS_BIAS, bool HAS_NBR>
__global__ __launch_bounds__(256)
void conv_kernel(const float* __restrict__ X, const float* __restrict__ W,
                 const float* __restrict__ bias, const int* __restrict__ nbr,
                 float* __restrict__ out, int M, int K) {
    __shared__ float Xs[TILE_M][CHUNK + 1];
    __shared__ float Ws[CHUNK][NFD];
    __shared__ int Idx[TILE_M];

    const int t  = threadIdx.x;
    const int tx = t & 15;            // col group: cols f = 2*tx + 32*j (+0/+1)
    const int ty = t >> 4;            // row group: rows ty*4 + r
    const int rowBase = blockIdx.x * TILE_M;

    unsigned long long acc[4][4];
    #pragma unroll
    for (int r = 0; r < 4; ++r)
        #pragma unroll
        for (int j = 0; j < 4; ++j) acc[r][j] = 0ULL;

    for (int k = 0; k < K; ++k) {
        if (t < TILE_M) {
            int gr = rowBase + t;
            int idx;
            if (HAS_NBR) idx = (gr < M) ? nbr[(size_t)k * M + gr] : -1;
            else         idx = (gr < M) ? gr : -1;
            Idx[t] = idx;
        }
        #pragma unroll
        for (int cc = 0; cc < CIN; cc += CHUNK) {
            __syncthreads();
            // load weight chunk [CHUNK x 128] (float4, coalesced)
            const float4* Wg = (const float4*)(W + ((size_t)k * CIN + cc) * NFD);
            #pragma unroll
            for (int it = 0; it < (CHUNK * NFD / 4) / 256; ++it) {
                int l  = t + it * 256;
                int c  = l >> 5;        // NFD/4 = 32 float4 per row
                int f4 = l & 31;
                ((float4*)&Ws[c][f4 * 4])[0] = Wg[c * 32 + f4];
            }
            // gather input chunk [TILE_M x CHUNK] (row-coalesced per warp)
            #pragma unroll
            for (int it = 0; it < (TILE_M * CHUNK) / 256; ++it) {
                int l = t + it * 256;
                int r = l >> 5;
                int c = l & 31;
                int idx = Idx[r];
                Xs[r][c] = (idx >= 0) ? X[(size_t)idx * CIN + cc + c] : 0.f;
            }
            __syncthreads();
            #pragma unroll
            for (int c = 0; c < CHUNK; ++c) {
                unsigned long long xx[4];
                #pragma unroll
                for (int r = 0; r < 4; ++r) {
                    float xv = Xs[ty * 4 + r][c];
                    asm("mov.b64 %0, {%1, %1};" : "=l"(xx[r]) : "f"(xv));
                }
                #pragma unroll
                for (int j = 0; j < 4; ++j) {
                    unsigned long long ww =
                        *(const unsigned long long*)&Ws[c][2 * tx + 32 * j];
                    #pragma unroll
                    for (int r = 0; r < 4; ++r) {
                        asm("fma.rn.f32x2 %0, %1, %2, %0;"
                            : "+l"(acc[r][j]) : "l"(xx[r]), "l"(ww));
                    }
                }
            }
        }
    }
    // epilogue
    #pragma unroll
    for (int r = 0; r < 4; ++r) {
        int gr = rowBase + ty * 4 + r;
        if (gr >= M) continue;
        #pragma unroll
        for (int j = 0; j < 4; ++j) {
            int f = 2 * tx + 32 * j;
            float lo, hi;
            asm("mov.b64 {%0, %1}, %2;" : "=f"(lo), "=f"(hi) : "l"(acc[r][j]));
            if (HAS_BIAS) { lo += bias[f]; hi += bias[f + 1]; }
            float2* o = (float2*)(out + (size_t)gr * NFD + f);
            if (ACCUM) { float2 p = *o; lo += p.x; hi += p.y; }
            *o = make_float2(lo, hi);
        }
    }
}

// ---------------- launch ----------------
extern "C" void kernel_launch(void* const* d_in, const int* in_sizes, int n_in,
                              void* d_out, int out_size) {
    const float* x     = (const float*)d_in[0];
    const float* t     = (const float*)d_in[1];
    const int*   b_idx = (const int*)  d_in[2];
    const int*   nbr   = (const int*)  d_in[3];
    const int*   nbrd  = (const int*)  d_in[4];
    const float* g1    = (const float*)d_in[5];
    const float* be1   = (const float*)d_in[6];
    const float* W1    = (const float*)d_in[7];
    const float* b1    = (const float*)d_in[8];
    const float* Wt    = (const float*)d_in[9];
    const float* bt    = (const float*)d_in[10];
    const float* g2    = (const float*)d_in[11];
    const float* be2   = (const float*)d_in[12];
    const float* W2    = (const float*)d_in[13];
    const float* b2    = (const float*)d_in[14];
    const float* Wid   = (const float*)d_in[15];
    const float* bid   = (const float*)d_in[16];
    const float* Wd    = (const float*)d_in[17];
    float* out = (float*)d_out;

    float *pa, *ph, *ph2, *ppart, *pmv, *ptp;
    cudaGetSymbolAddress((void**)&pa,    g_a);
    cudaGetSymbolAddress((void**)&ph,    g_h);
    cudaGetSymbolAddress((void**)&ph2,   g_h2);
    cudaGetSymbolAddress((void**)&ppart, g_part);
    cudaGetSymbolAddress((void**)&pmv,   g_mv);
    cudaGetSymbolAddress((void**)&ptp,   g_tp);

    const float invn = 1.0f / (float)NN;
    const int convGrid = (NN + TILE_M - 1) / TILE_M;   // 3125
    const int downGrid = (NDD + TILE_M - 1) / TILE_M;  // 391

    // ---- BN1(x) + SiLU -> a1 ----
    bn_stats_kernel<NI><<<STATS_BLOCKS, 256>>>(x, NN, ppart);
    bn_finalize_kernel<NI><<<1, NI>>>(ppart, STATS_BLOCKS, invn, g1, be1, pmv);
    {
        int n4 = NN * NI / 4;
        bn_apply_silu_kernel<NI><<<(n4 + 255) / 256, 256>>>((const float4*)x, pmv,
                                                            (float4*)pa, n4);
    }
    // ---- conv1 -> h ----
    conv_kernel<NI, false, true, true><<<convGrid, 256>>>(pa, W1, b1, nbr, ph, NN, KK);
    // ---- time projection + FiLM ----
    tproj_kernel<<<1, 256>>>(t, Wt, bt, ptp);
    {
        int n4 = NN * NFD / 4;
        film_kernel<<<(n4 + 255) / 256, 256>>>((float4*)ph, b_idx, ptp, n4);
    }
    // ---- BN2(h) + SiLU -> a2 ----
    bn_stats_kernel<NFD><<<STATS_BLOCKS, 256>>>(ph, NN, ppart);
    bn_finalize_kernel<NFD><<<1, NFD>>>(ppart, STATS_BLOCKS, invn, g2, be2, pmv);
    {
        int n4 = NN * NFD / 4;
        bn_apply_silu_kernel<NFD><<<(n4 + 255) / 256, 256>>>((const float4*)ph, pmv,
                                                             (float4*)pa, n4);
    }
    // ---- conv2 -> h2 ----
    conv_kernel<NFD, false, true, true><<<convGrid, 256>>>(pa, W2, b2, nbr, ph2, NN, KK);
    // ---- idconv residual: h2 += x @ Wid + bid ----
    conv_kernel<NI, true, true, false><<<convGrid, 256>>>(x, Wid, bid, nullptr, ph2, NN, 1);
    // ---- strided down conv -> out [ND, NF] ----
    conv_kernel<NFD, false, false, true><<<downGrid, 256>>>(ph2, Wd, nullptr, nbrd, out,
                                                            NDD, KDD);
    (void)in_sizes; (void)n_in; (void)out_size;
}